// round 1
// baseline (speedup 1.0000x reference)
#include <cuda_runtime.h>

#define DD 128
#define NMAX 50048

// Scratch (device globals — no allocation allowed in kernel_launch)
__device__ float g_hs[(size_t)NMAX * DD];   // dinv-scaled GEMM output (gather source)
__device__ float g_acc[(size_t)NMAX * DD];  // scatter accumulator (init = hs for self-loop)
__device__ float g_h1[(size_t)NMAX * DD];   // layer-1 activation
__device__ float g_deg[NMAX];
__device__ float g_dinv[NMAX];
__device__ int   g_idx64;                   // 1 if edge_index is int64, 0 if int32

// ---------------------------------------------------------------------------
// Edge dtype detection: if data is really int32, reading int64 fuses two valid
// indices -> value >= 2^32 >> n with overwhelming probability over 1024 samples.
__global__ void k_detect(const long long* __restrict__ e64, int twoE, int n) {
    __shared__ int bad;
    if (threadIdx.x == 0) bad = 0;
    __syncthreads();
    int lim = (twoE / 2 < 1024) ? (twoE / 2) : 1024;
    for (int i = threadIdx.x; i < lim; i += blockDim.x) {
        long long v = e64[i];
        if (v < 0 || v >= (long long)n) bad = 1;  // benign race
    }
    __syncthreads();
    if (threadIdx.x == 0) g_idx64 = bad ? 0 : 1;
}

__global__ void k_deg_init(int n) {
    int i = blockIdx.x * blockDim.x + threadIdx.x;
    if (i < n) g_deg[i] = 1.0f;  // self-loop
}

__global__ void k_deg_count(const long long* __restrict__ e64,
                            const int* __restrict__ e32, int E) {
    int e = blockIdx.x * blockDim.x + threadIdx.x;
    if (e >= E) return;
    int c = g_idx64 ? (int)e64[E + e] : e32[E + e];
    atomicAdd(&g_deg[c], 1.0f);
}

__global__ void k_dinv(int n) {
    int i = blockIdx.x * blockDim.x + threadIdx.x;
    if (i < n) g_dinv[i] = rsqrtf(g_deg[i]);  // deg >= 1 always
}

// ---------------------------------------------------------------------------
// GEMM: hs[r][c] = dinv[r] * sum_k X[r][k] * W[k][c]; also acc = hs (self-loop init).
// Block: 256 threads -> 64 rows x 128 cols. Smem: W full (64KB) + X tile (32KB).
__global__ void k_gemm(const float* __restrict__ X, const float* __restrict__ W, int n) {
    extern __shared__ float sm[];
    float* Ws = sm;             // 128*128
    float* xs = sm + 128 * 128; // 64*128
    int t = threadIdx.x;
    int row0 = blockIdx.x * 64;

    float4* Ws4 = (float4*)Ws;
    const float4* W4 = (const float4*)W;
#pragma unroll
    for (int i = 0; i < 16; i++) Ws4[t + i * 256] = W4[t + i * 256];

    float4* xs4 = (float4*)xs;
    const float4* X4 = (const float4*)X;
#pragma unroll
    for (int i = 0; i < 8; i++) {
        int f = t + i * 256;           // 0..2047 float4s
        int lr = f >> 5, c4 = f & 31;
        int gr = row0 + lr;
        float4 v = make_float4(0.f, 0.f, 0.f, 0.f);
        if (gr < n) v = X4[(size_t)gr * 32 + c4];
        xs4[f] = v;
    }
    __syncthreads();

    int c0 = (t & 31) * 4;   // 4 contiguous cols
    int r0 = (t >> 5) * 8;   // 8 rows
    float acc[8][4];
#pragma unroll
    for (int i = 0; i < 8; i++)
#pragma unroll
        for (int j = 0; j < 4; j++) acc[i][j] = 0.f;

#pragma unroll 8
    for (int k = 0; k < 128; k++) {
        float4 w = *(const float4*)(Ws + k * 128 + c0);
#pragma unroll
        for (int i = 0; i < 8; i++) {
            float xv = xs[(r0 + i) * 128 + k];
            acc[i][0] = fmaf(xv, w.x, acc[i][0]);
            acc[i][1] = fmaf(xv, w.y, acc[i][1]);
            acc[i][2] = fmaf(xv, w.z, acc[i][2]);
            acc[i][3] = fmaf(xv, w.w, acc[i][3]);
        }
    }

#pragma unroll
    for (int i = 0; i < 8; i++) {
        int gr = row0 + r0 + i;
        if (gr < n) {
            float dv = g_dinv[gr];
            float4 o = make_float4(acc[i][0] * dv, acc[i][1] * dv,
                                   acc[i][2] * dv, acc[i][3] * dv);
            *(float4*)(g_hs  + (size_t)gr * 128 + c0) = o;
            *(float4*)(g_acc + (size_t)gr * 128 + c0) = o;
        }
    }
}

// ---------------------------------------------------------------------------
// Scatter: one warp per edge (4 edges per warp), lane l owns floats [4l,4l+4).
// Per edge: 1 LDG.128 gather + 1 RED.128 vector atomic.
__global__ void k_scatter(const long long* __restrict__ e64,
                          const int* __restrict__ e32, int E) {
    int w = (blockIdx.x * blockDim.x + threadIdx.x) >> 5;
    int lane = threadIdx.x & 31;
    int idx64 = g_idx64;
    int base = w * 4;
#pragma unroll
    for (int j = 0; j < 4; j++) {
        int e = base + j;
        if (e >= E) return;
        int r, c;
        if (idx64) { r = (int)e64[e]; c = (int)e64[E + e]; }
        else       { r = e32[e];      c = e32[E + e]; }
        float4 v = *(const float4*)(g_hs + (size_t)r * 128 + lane * 4);
        float* dst = g_acc + (size_t)c * 128 + lane * 4;
        asm volatile("red.global.add.v4.f32 [%0], {%1, %2, %3, %4};"
                     :: "l"(dst), "f"(v.x), "f"(v.y), "f"(v.z), "f"(v.w)
                     : "memory");
    }
}

// ---------------------------------------------------------------------------
// Epilogue: out = relu(dinv[r] * acc + b)
__global__ void k_finish(const float* __restrict__ b, float* __restrict__ out, int n) {
    int i = blockIdx.x * blockDim.x + threadIdx.x;  // one float4 each
    if (i >= n * 32) return;
    int r = i >> 5, c4 = i & 31;
    float dv = g_dinv[r];
    float4 a = ((const float4*)g_acc)[i];
    float4 bb = ((const float4*)b)[c4];
    float4 o;
    o.x = fmaxf(fmaf(a.x, dv, bb.x), 0.f);
    o.y = fmaxf(fmaf(a.y, dv, bb.y), 0.f);
    o.z = fmaxf(fmaf(a.z, dv, bb.z), 0.f);
    o.w = fmaxf(fmaf(a.w, dv, bb.w), 0.f);
    ((float4*)out)[i] = o;
}

// ---------------------------------------------------------------------------
extern "C" void kernel_launch(void* const* d_in, const int* in_sizes, int n_in,
                              void* d_out, int out_size) {
    const float* x  = (const float*)d_in[0];
    const void*  ed = d_in[1];
    const float* W1 = (const float*)d_in[2];
    const float* b1 = (const float*)d_in[3];
    const float* W2 = (const float*)d_in[4];
    const float* b2 = (const float*)d_in[5];
    float* out = (float*)d_out;

    int n = in_sizes[0] / DD;       // 50000
    int E = in_sizes[1] / 2;        // 800000

    const long long* e64 = (const long long*)ed;
    const int*       e32 = (const int*)ed;

    float* h1;
    cudaGetSymbolAddress((void**)&h1, g_h1);

    cudaFuncSetAttribute(k_gemm, cudaFuncAttributeMaxDynamicSharedMemorySize, 98304);

    int nb_n   = (n + 255) / 256;
    int nb_e   = (E + 255) / 256;
    int nb_g   = (n + 63) / 64;
    int nb_s   = (E + 31) / 32;          // 8 warps/block * 4 edges/warp
    int nb_f   = (n * 32 + 255) / 256;

    k_detect<<<1, 256>>>(e64, 2 * E, n);
    k_deg_init<<<nb_n, 256>>>(n);
    k_deg_count<<<nb_e, 256>>>(e64, e32, E);
    k_dinv<<<nb_n, 256>>>(n);

    // Layer 1
    k_gemm<<<nb_g, 256, 98304>>>(x, W1, n);
    k_scatter<<<nb_s, 256>>>(e64, e32, E);
    k_finish<<<nb_f, 256>>>(b1, h1, n);

    // Layer 2
    k_gemm<<<nb_g, 256, 98304>>>(h1, W2, n);
    k_scatter<<<nb_s, 256>>>(e64, e32, E);
    k_finish<<<nb_f, 256>>>(b2, out, n);
}

// round 3
// speedup vs baseline: 1.0246x; 1.0246x over previous
#include <cuda_runtime.h>
#include <cuda_bf16.h>
#include <cstdint>

#define DD 128
#define NMAX 50048
#define TILE_M 128
#define PADH 136            // smem row stride in halves (272 B)

// ---------------- device scratch (no allocation allowed) --------------------
__device__ float g_hs[(size_t)NMAX * DD];   // dinv-scaled GEMM output (gather src)
__device__ float g_acc[(size_t)NMAX * DD];  // scatter accumulator (init = hs)
__device__ float g_deg[NMAX];
__device__ int   g_idx64;
// W preformatted as bf16 hi/lo, plain row-major [k][n]
__device__ __nv_bfloat16 g_W1h[16384], g_W1l[16384], g_W2h[16384], g_W2l[16384];

// ---------------- warp MMA helpers -----------------------------------------
__device__ __forceinline__ uint32_t smem_to_u32(const void* p) {
    uint32_t a;
    asm("{ .reg .u64 t; cvta.to.shared.u64 t, %1; cvt.u32.u64 %0, t; }" : "=r"(a) : "l"(p));
    return a;
}
__device__ __forceinline__ void ldsm4(uint32_t* r, uint32_t addr) {
    asm volatile("ldmatrix.sync.aligned.m8n8.x4.shared.b16 {%0,%1,%2,%3}, [%4];"
                 : "=r"(r[0]), "=r"(r[1]), "=r"(r[2]), "=r"(r[3]) : "r"(addr));
}
__device__ __forceinline__ void ldsm4t(uint32_t* r, uint32_t addr) {
    asm volatile("ldmatrix.sync.aligned.m8n8.x4.trans.shared.b16 {%0,%1,%2,%3}, [%4];"
                 : "=r"(r[0]), "=r"(r[1]), "=r"(r[2]), "=r"(r[3]) : "r"(addr));
}
__device__ __forceinline__ void mma16816(float* c, const uint32_t* a, const uint32_t* b) {
    asm volatile(
        "mma.sync.aligned.m16n8k16.row.col.f32.bf16.bf16.f32 "
        "{%0,%1,%2,%3}, {%4,%5,%6,%7}, {%8,%9}, {%0,%1,%2,%3};"
        : "+f"(c[0]), "+f"(c[1]), "+f"(c[2]), "+f"(c[3])
        : "r"(a[0]), "r"(a[1]), "r"(a[2]), "r"(a[3]), "r"(b[0]), "r"(b[1]));
}

// ---------------------------------------------------------------------------
// Fused preprocess: deg init (+ edge dtype detect in block 0) + W1/W2 bf16 split.
__global__ void k_pre(const long long* __restrict__ e64,
                      const float* __restrict__ W1, const float* __restrict__ W2,
                      int E, int n) {
    int b = blockIdx.x;
    if (b < 196) {
        int i = b * 256 + threadIdx.x;
        if (i < n) g_deg[i] = 1.0f;  // self-loop
        if (b == 0) {
            __shared__ int bad;
            if (threadIdx.x == 0) bad = 0;
            __syncthreads();
            int lim = (E < 1024) ? E : 1024;
            for (int j = threadIdx.x; j < lim; j += 256) {
                long long v = e64[j];
                if (v < 0 || v >= (long long)n) bad = 1;  // benign race
            }
            __syncthreads();
            if (threadIdx.x == 0) g_idx64 = bad ? 0 : 1;
        }
    } else {
        int idx = (b - 196) * 256 + threadIdx.x;  // 0..16383 = k*128+n
        float w1 = W1[idx], w2 = W2[idx];
        __nv_bfloat16 h1 = __float2bfloat16(w1);
        __nv_bfloat16 h2 = __float2bfloat16(w2);
        g_W1h[idx] = h1;
        g_W1l[idx] = __float2bfloat16(w1 - __bfloat162float(h1));
        g_W2h[idx] = h2;
        g_W2l[idx] = __float2bfloat16(w2 - __bfloat162float(h2));
    }
}

__global__ void k_deg_count(const long long* __restrict__ e64,
                            const int* __restrict__ e32, int E) {
    int e = blockIdx.x * blockDim.x + threadIdx.x;
    if (e >= E) return;
    int c = g_idx64 ? (int)e64[E + e] : e32[E + e];
    atomicAdd(&g_deg[c], 1.0f);
}

// ---------------------------------------------------------------------------
// HMMA split-bf16 GEMM: hs[r] = rsqrt(deg[r]) * (A @ W); acc = hs (self-loop).
// mode 0: A = Asrc (fp32)
// mode 1: A = relu(rsqrt(deg[r]) * Asrc[r] + bias)  (fuses layer-1 finish)
// Block: 256 thr = 8 warps; warp w owns rows [16w,16w+16) of a 128-row tile.
__global__ void __launch_bounds__(256, 1) k_gemm(
    const float* __restrict__ Asrc,
    const __nv_bfloat16* __restrict__ Wh, const __nv_bfloat16* __restrict__ Wl,
    const float* __restrict__ bias, int mode, int n)
{
    extern __shared__ char smem[];
    const uint32_t SZ = 128 * PADH * 2;           // 34816 B per tile
    const uint32_t OFF_AH = 0, OFF_AL = SZ, OFF_WH = 2 * SZ, OFF_WL = 3 * SZ;
    uint32_t sb = smem_to_u32(smem);
    int tid = threadIdx.x, wid = tid >> 5, lane = tid & 31;
    int row0 = blockIdx.x * TILE_M;

    // Copy W hi/lo into padded smem (uint4 = 8 halves; 272-byte rows keep 16B align).
    {
        const uint4* sh = (const uint4*)Wh;
        const uint4* sl = (const uint4*)Wl;
#pragma unroll
        for (int i = 0; i < 8; i++) {
            int f = tid + i * 256;               // 0..2047
            int k = f >> 4, n8 = (f & 15) * 8;
            uint32_t doff = (uint32_t)k * 272 + n8 * 2;
            *(uint4*)(smem + OFF_WH + doff) = sh[f];
            *(uint4*)(smem + OFF_WL + doff) = sl[f];
        }
    }

    // A tile: load fp32 (+ optional fused relu epilogue of prev layer), split hi/lo.
    for (int r = wid; r < 128; r += 8) {
        int gr = row0 + r;
        float4 v = make_float4(0.f, 0.f, 0.f, 0.f);
        if (gr < n) {
            v = ((const float4*)Asrc)[(size_t)gr * 32 + lane];
            if (mode) {
                float dv = rsqrtf(g_deg[gr]);
                float4 bb = ((const float4*)bias)[lane];
                v.x = fmaxf(fmaf(v.x, dv, bb.x), 0.f);
                v.y = fmaxf(fmaf(v.y, dv, bb.y), 0.f);
                v.z = fmaxf(fmaf(v.z, dv, bb.z), 0.f);
                v.w = fmaxf(fmaf(v.w, dv, bb.w), 0.f);
            }
        }
        __nv_bfloat16 hx = __float2bfloat16(v.x), hy = __float2bfloat16(v.y);
        __nv_bfloat16 hz = __float2bfloat16(v.z), hw = __float2bfloat16(v.w);
        __nv_bfloat16 lx = __float2bfloat16(v.x - __bfloat162float(hx));
        __nv_bfloat16 ly = __float2bfloat16(v.y - __bfloat162float(hy));
        __nv_bfloat16 lz = __float2bfloat16(v.z - __bfloat162float(hz));
        __nv_bfloat16 lw = __float2bfloat16(v.w - __bfloat162float(hw));
        uint32_t o = (uint32_t)r * 272 + lane * 8;   // halves: r*136 + lane*4
        *(__nv_bfloat162*)(smem + OFF_AH + o)     = __nv_bfloat162(hx, hy);
        *(__nv_bfloat162*)(smem + OFF_AH + o + 4) = __nv_bfloat162(hz, hw);
        *(__nv_bfloat162*)(smem + OFF_AL + o)     = __nv_bfloat162(lx, ly);
        *(__nv_bfloat162*)(smem + OFF_AL + o + 4) = __nv_bfloat162(lz, lw);
    }
    __syncthreads();

    // ldmatrix lane addressing
    int lrow  = (lane & 7) + ((lane >> 3) & 1) * 8;  // 0..15
    int lcol8 = ((lane >> 4) & 1) * 8;               // 0 or 8
    int mr = wid * 16;
    uint32_t aRow = (uint32_t)(mr + lrow) * 272 + lcol8 * 2;  // + kb*32
    uint32_t bRow = (uint32_t)lrow * 272 + lcol8 * 2;         // + kb*16*272 + nb*32

    float acc[16][4];
#pragma unroll
    for (int t = 0; t < 16; t++)
#pragma unroll
        for (int j = 0; j < 4; j++) acc[t][j] = 0.f;

#pragma unroll
    for (int pass = 0; pass < 3; pass++) {
        uint32_t Ab = sb + ((pass == 2) ? OFF_AL : OFF_AH);
        uint32_t Bb = sb + ((pass == 1) ? OFF_WL : OFF_WH);
#pragma unroll
        for (int kb = 0; kb < 8; kb++) {
            uint32_t ra[4];
            ldsm4(ra, Ab + aRow + kb * 32);
            uint32_t bk = Bb + bRow + (uint32_t)kb * 16 * 272;
#pragma unroll
            for (int nb = 0; nb < 8; nb++) {
                uint32_t rb[4];
                ldsm4t(rb, bk + nb * 32);
                mma16816(acc[2 * nb],     ra, rb);
                mma16816(acc[2 * nb + 1], ra, rb + 2);
            }
        }
    }

    // Epilogue: scale by dinv, store hs + acc.
    int g = lane >> 2, tig = lane & 3;
    int r0g = row0 + mr + g, r1g = r0g + 8;
    float dv0 = (r0g < n) ? rsqrtf(g_deg[r0g]) : 0.f;
    float dv1 = (r1g < n) ? rsqrtf(g_deg[r1g]) : 0.f;
#pragma unroll
    for (int t = 0; t < 16; t++) {
        int col = t * 8 + tig * 2;
        if (r0g < n) {
            float2 o = make_float2(acc[t][0] * dv0, acc[t][1] * dv0);
            *(float2*)(g_hs  + (size_t)r0g * 128 + col) = o;
            *(float2*)(g_acc + (size_t)r0g * 128 + col) = o;
        }
        if (r1g < n) {
            float2 o = make_float2(acc[t][2] * dv1, acc[t][3] * dv1);
            *(float2*)(g_hs  + (size_t)r1g * 128 + col) = o;
            *(float2*)(g_acc + (size_t)r1g * 128 + col) = o;
        }
    }
}

// ---------------------------------------------------------------------------
// Scatter: 4 edges/warp; per edge 1 LDG.128 gather + 1 RED.128 vector atomic.
__global__ void k_scatter(const long long* __restrict__ e64,
                          const int* __restrict__ e32, int E) {
    int w = (blockIdx.x * blockDim.x + threadIdx.x) >> 5;
    int lane = threadIdx.x & 31;
    int idx64 = g_idx64;
    int base = w * 4;
#pragma unroll
    for (int j = 0; j < 4; j++) {
        int e = base + j;
        if (e >= E) return;
        int r, c;
        if (idx64) { r = (int)e64[e]; c = (int)e64[E + e]; }
        else       { r = e32[e];      c = e32[E + e]; }
        float4 v = *(const float4*)(g_hs + (size_t)r * 128 + lane * 4);
        float* dst = g_acc + (size_t)c * 128 + lane * 4;
        asm volatile("red.global.add.v4.f32 [%0], {%1, %2, %3, %4};"
                     :: "l"(dst), "f"(v.x), "f"(v.y), "f"(v.z), "f"(v.w) : "memory");
    }
}

// ---------------------------------------------------------------------------
__global__ void k_finish(const float* __restrict__ b, float* __restrict__ out, int n) {
    int i = blockIdx.x * blockDim.x + threadIdx.x;  // one float4 each
    if (i >= n * 32) return;
    int r = i >> 5, c4 = i & 31;
    float dv = rsqrtf(g_deg[r]);
    float4 a = ((const float4*)g_acc)[i];
    float4 bb = ((const float4*)b)[c4];
    float4 o;
    o.x = fmaxf(fmaf(a.x, dv, bb.x), 0.f);
    o.y = fmaxf(fmaf(a.y, dv, bb.y), 0.f);
    o.z = fmaxf(fmaf(a.z, dv, bb.z), 0.f);
    o.w = fmaxf(fmaf(a.w, dv, bb.w), 0.f);
    ((float4*)out)[i] = o;
}

// ---------------------------------------------------------------------------
extern "C" void kernel_launch(void* const* d_in, const int* in_sizes, int n_in,
                              void* d_out, int out_size) {
    const float* x  = (const float*)d_in[0];
    const void*  ed = d_in[1];
    const float* W1 = (const float*)d_in[2];
    const float* b1 = (const float*)d_in[3];
    const float* W2 = (const float*)d_in[4];
    const float* b2 = (const float*)d_in[5];
    float* out = (float*)d_out;

    int n = in_sizes[0] / DD;   // 50000
    int E = in_sizes[1] / 2;    // 800000

    const long long* e64 = (const long long*)ed;
    const int*       e32 = (const int*)ed;

    void *acc_p, *w1h, *w1l, *w2h, *w2l;
    cudaGetSymbolAddress(&acc_p, g_acc);
    cudaGetSymbolAddress(&w1h, g_W1h);
    cudaGetSymbolAddress(&w1l, g_W1l);
    cudaGetSymbolAddress(&w2h, g_W2h);
    cudaGetSymbolAddress(&w2l, g_W2l);

    const int SMEM = 4 * 128 * PADH * 2;   // 139264
    cudaFuncSetAttribute(k_gemm, cudaFuncAttributeMaxDynamicSharedMemorySize, SMEM);

    int tiles = (n + TILE_M - 1) / TILE_M;          // 391
    int nb_e  = (E + 255) / 256;
    int nb_s  = (E + 31) / 32;
    int nb_f  = (n * 32 + 255) / 256;

    k_pre<<<196 + 64, 256>>>(e64, W1, W2, E, n);
    k_deg_count<<<nb_e, 256>>>(e64, e32, E);

    // Layer 1
    k_gemm<<<tiles, 256, SMEM>>>(x, (const __nv_bfloat16*)w1h, (const __nv_bfloat16*)w1l,
                                 b1, 0, n);
    k_scatter<<<nb_s, 256>>>(e64, e32, E);

    // Layer 2 (layer-1 finish fused into A-tile load)
    k_gemm<<<tiles, 256, SMEM>>>((const float*)acc_p, (const __nv_bfloat16*)w2h,
                                 (const __nv_bfloat16*)w2l, b1, 1, n);
    k_scatter<<<nb_s, 256>>>(e64, e32, E);
    k_finish<<<nb_f, 256>>>(b2, out, n);
}

// round 4
// speedup vs baseline: 1.3793x; 1.3462x over previous
#include <cuda_runtime.h>
#include <cuda_bf16.h>
#include <cstdint>

#define DD 128
#define NMAX 50048
#define EMAX 1000000
#define TILE_M 128
#define PADH 136            // smem row stride in halves (272 B)
#define NB_CSR 148

// ---------------- device scratch (no allocation allowed) --------------------
__device__ float g_hs[(size_t)NMAX * DD];   // dinv-scaled GEMM output (gather src)
__device__ float g_h1[(size_t)NMAX * DD];   // layer-1 activation
__device__ int   g_cnt[NMAX];               // in-degree (excl self)
__device__ int   g_off[NMAX];               // CSR offsets
__device__ int   g_cur[NMAX];               // bucket cursors
__device__ int   g_srt[EMAX];               // sources grouped by destination
__device__ int   g_bsum[NB_CSR];
__device__ int   g_idx64;
__device__ int   g_bar_cnt = 0;
__device__ volatile int g_bar_gen = 0;
// W preformatted as bf16 hi/lo, row-major [k][n]
__device__ __nv_bfloat16 g_W1h[16384], g_W1l[16384], g_W2h[16384], g_W2l[16384];

// ---------------- helpers ---------------------------------------------------
__device__ __forceinline__ uint32_t smem_to_u32(const void* p) {
    uint32_t a;
    asm("{ .reg .u64 t; cvta.to.shared.u64 t, %1; cvt.u32.u64 %0, t; }" : "=r"(a) : "l"(p));
    return a;
}
__device__ __forceinline__ void ldsm4(uint32_t* r, uint32_t addr) {
    asm volatile("ldmatrix.sync.aligned.m8n8.x4.shared.b16 {%0,%1,%2,%3}, [%4];"
                 : "=r"(r[0]), "=r"(r[1]), "=r"(r[2]), "=r"(r[3]) : "r"(addr));
}
__device__ __forceinline__ void ldsm4t(uint32_t* r, uint32_t addr) {
    asm volatile("ldmatrix.sync.aligned.m8n8.x4.trans.shared.b16 {%0,%1,%2,%3}, [%4];"
                 : "=r"(r[0]), "=r"(r[1]), "=r"(r[2]), "=r"(r[3]) : "r"(addr));
}
__device__ __forceinline__ void mma16816(float* c, const uint32_t* a, const uint32_t* b) {
    asm volatile(
        "mma.sync.aligned.m16n8k16.row.col.f32.bf16.bf16.f32 "
        "{%0,%1,%2,%3}, {%4,%5,%6,%7}, {%8,%9}, {%0,%1,%2,%3};"
        : "+f"(c[0]), "+f"(c[1]), "+f"(c[2]), "+f"(c[3])
        : "r"(a[0]), "r"(a[1]), "r"(a[2]), "r"(a[3]), "r"(b[0]), "r"(b[1]));
}
__device__ __forceinline__ void gridbar() {
    __syncthreads();
    if (threadIdx.x == 0) {
        __threadfence();
        int g = g_bar_gen;
        if (atomicAdd(&g_bar_cnt, 1) == NB_CSR - 1) {
            g_bar_cnt = 0;
            __threadfence();
            g_bar_gen = g + 1;
        } else {
            while (g_bar_gen == g) __nanosleep(20);
        }
    }
    __syncthreads();
}

// ---------------------------------------------------------------------------
// Preprocess: W1/W2 bf16 hi/lo split + edge dtype detect.
__global__ void k_pre(const long long* __restrict__ e64,
                      const float* __restrict__ W1, const float* __restrict__ W2,
                      int E, int n) {
    int b = blockIdx.x;
    if (b == 64) {
        __shared__ int bad;
        if (threadIdx.x == 0) bad = 0;
        __syncthreads();
        int lim = (E < 1024) ? E : 1024;
        for (int j = threadIdx.x; j < lim; j += 256) {
            long long v = e64[j];
            if (v < 0 || v >= (long long)n) bad = 1;  // benign race
        }
        __syncthreads();
        if (threadIdx.x == 0) g_idx64 = bad ? 0 : 1;
        return;
    }
    int idx = b * 256 + threadIdx.x;  // 0..16383 = k*128+n
    float w1 = W1[idx], w2 = W2[idx];
    __nv_bfloat16 h1 = __float2bfloat16(w1);
    __nv_bfloat16 h2 = __float2bfloat16(w2);
    g_W1h[idx] = h1;
    g_W1l[idx] = __float2bfloat16(w1 - __bfloat162float(h1));
    g_W2h[idx] = h2;
    g_W2l[idx] = __float2bfloat16(w2 - __bfloat162float(h2));
}

// ---------------------------------------------------------------------------
// CSR build in ONE persistent launch: zero -> histogram -> scan -> bucket.
__global__ void __launch_bounds__(256) k_csr(const long long* __restrict__ e64,
                                             const int* __restrict__ e32,
                                             int E, int n) {
    __shared__ int sc[352];
    __shared__ int ssum;
    int tid = threadIdx.x, bid = blockIdx.x;
    int idx64 = g_idx64;

    // P0: zero counters
    for (int i = bid * 256 + tid; i < n; i += NB_CSR * 256) g_cnt[i] = 0;
    gridbar();

    // P1: histogram over destinations
    for (int e = bid * 256 + tid; e < E; e += NB_CSR * 256) {
        int c = idx64 ? (int)e64[E + e] : e32[E + e];
        atomicAdd(&g_cnt[c], 1);
    }
    gridbar();

    // P2: load my chunk into smem + block sum
    int chunk = (n + NB_CSR - 1) / NB_CSR;            // <= 339
    int base = bid * chunk;
    int len = n - base; if (len > chunk) len = chunk; if (len < 0) len = 0;
    int s = 0;
    for (int i = tid; i < len; i += 256) { int v = g_cnt[base + i]; sc[i] = v; s += v; }
    if (tid == 0) ssum = 0;
    __syncthreads();
#pragma unroll
    for (int o = 16; o > 0; o >>= 1) s += __shfl_down_sync(0xffffffffu, s, o);
    if ((tid & 31) == 0) atomicAdd(&ssum, s);
    __syncthreads();
    if (tid == 0) g_bsum[bid] = ssum;
    gridbar();

    // P3: scan block sums (block 0, thread 0: 148 elements)
    if (bid == 0 && tid == 0) {
        int a = 0;
        for (int i = 0; i < NB_CSR; i++) { int t = g_bsum[i]; g_bsum[i] = a; a += t; }
    }
    gridbar();

    // P4: serial exclusive scan of my chunk in smem, then parallel store
    if (tid == 0) {
        int a = g_bsum[bid];
        for (int i = 0; i < len; i++) { int t = sc[i]; sc[i] = a; a += t; }
    }
    __syncthreads();
    for (int i = tid; i < len; i += 256) {
        int o = sc[i];
        g_off[base + i] = o;
        g_cur[base + i] = o;
    }
    gridbar();

    // P5: bucket sources by destination
    for (int e = bid * 256 + tid; e < E; e += NB_CSR * 256) {
        int r, c;
        if (idx64) { r = (int)e64[e]; c = (int)e64[E + e]; }
        else       { r = e32[e];      c = e32[E + e]; }
        int pos = atomicAdd(&g_cur[c], 1);
        g_srt[pos] = r;
    }
}

// ---------------------------------------------------------------------------
// HMMA split-bf16 GEMM: hs[r] = rsqrt(deg[r]) * (A @ W).
__global__ void __launch_bounds__(256, 1) k_gemm(
    const float* __restrict__ Asrc,
    const __nv_bfloat16* __restrict__ Wh, const __nv_bfloat16* __restrict__ Wl, int n)
{
    extern __shared__ char smem[];
    const uint32_t SZ = 128 * PADH * 2;
    const uint32_t OFF_AH = 0, OFF_AL = SZ, OFF_WH = 2 * SZ, OFF_WL = 3 * SZ;
    uint32_t sb = smem_to_u32(smem);
    int tid = threadIdx.x, wid = tid >> 5, lane = tid & 31;
    int row0 = blockIdx.x * TILE_M;

    {
        const uint4* sh = (const uint4*)Wh;
        const uint4* sl = (const uint4*)Wl;
#pragma unroll
        for (int i = 0; i < 8; i++) {
            int f = tid + i * 256;
            int k = f >> 4, n8 = (f & 15) * 8;
            uint32_t doff = (uint32_t)k * 272 + n8 * 2;
            *(uint4*)(smem + OFF_WH + doff) = sh[f];
            *(uint4*)(smem + OFF_WL + doff) = sl[f];
        }
    }

    for (int r = wid; r < 128; r += 8) {
        int gr = row0 + r;
        float4 v = make_float4(0.f, 0.f, 0.f, 0.f);
        if (gr < n) v = ((const float4*)Asrc)[(size_t)gr * 32 + lane];
        __nv_bfloat16 hx = __float2bfloat16(v.x), hy = __float2bfloat16(v.y);
        __nv_bfloat16 hz = __float2bfloat16(v.z), hw = __float2bfloat16(v.w);
        __nv_bfloat16 lx = __float2bfloat16(v.x - __bfloat162float(hx));
        __nv_bfloat16 ly = __float2bfloat16(v.y - __bfloat162float(hy));
        __nv_bfloat16 lz = __float2bfloat16(v.z - __bfloat162float(hz));
        __nv_bfloat16 lw = __float2bfloat16(v.w - __bfloat162float(hw));
        uint32_t o = (uint32_t)r * 272 + lane * 8;
        *(__nv_bfloat162*)(smem + OFF_AH + o)     = __nv_bfloat162(hx, hy);
        *(__nv_bfloat162*)(smem + OFF_AH + o + 4) = __nv_bfloat162(hz, hw);
        *(__nv_bfloat162*)(smem + OFF_AL + o)     = __nv_bfloat162(lx, ly);
        *(__nv_bfloat162*)(smem + OFF_AL + o + 4) = __nv_bfloat162(lz, lw);
    }
    __syncthreads();

    int lrow  = (lane & 7) + ((lane >> 3) & 1) * 8;
    int lcol8 = ((lane >> 4) & 1) * 8;
    int mr = wid * 16;
    uint32_t aRow = (uint32_t)(mr + lrow) * 272 + lcol8 * 2;
    uint32_t bRow = (uint32_t)lrow * 272 + lcol8 * 2;

    float acc[16][4];
#pragma unroll
    for (int t = 0; t < 16; t++)
#pragma unroll
        for (int j = 0; j < 4; j++) acc[t][j] = 0.f;

#pragma unroll
    for (int pass = 0; pass < 3; pass++) {
        uint32_t Ab = sb + ((pass == 2) ? OFF_AL : OFF_AH);
        uint32_t Bb = sb + ((pass == 1) ? OFF_WL : OFF_WH);
#pragma unroll
        for (int kb = 0; kb < 8; kb++) {
            uint32_t ra[4];
            ldsm4(ra, Ab + aRow + kb * 32);
            uint32_t bk = Bb + bRow + (uint32_t)kb * 16 * 272;
#pragma unroll
            for (int nb = 0; nb < 8; nb++) {
                uint32_t rb[4];
                ldsm4t(rb, bk + nb * 32);
                mma16816(acc[2 * nb],     ra, rb);
                mma16816(acc[2 * nb + 1], ra, rb + 2);
            }
        }
    }

    int g = lane >> 2, tig = lane & 3;
    int r0g = row0 + mr + g, r1g = r0g + 8;
    float dv0 = (r0g < n) ? rsqrtf((float)(g_cnt[r0g] + 1)) : 0.f;
    float dv1 = (r1g < n) ? rsqrtf((float)(g_cnt[r1g] + 1)) : 0.f;
#pragma unroll
    for (int t = 0; t < 16; t++) {
        int col = t * 8 + tig * 2;
        if (r0g < n)
            *(float2*)(g_hs + (size_t)r0g * 128 + col) =
                make_float2(acc[t][0] * dv0, acc[t][1] * dv0);
        if (r1g < n)
            *(float2*)(g_hs + (size_t)r1g * 128 + col) =
                make_float2(acc[t][2] * dv1, acc[t][3] * dv1);
    }
}

// ---------------------------------------------------------------------------
// Pull aggregation + full epilogue: out[c] = relu(dinv[c]*(hs[c] + sum_nbr hs[r]) + b)
// One warp per destination node; lane owns float4 [4*lane, 4*lane+4).
__global__ void __launch_bounds__(256) k_agg(const float* __restrict__ bias,
                                             float* __restrict__ out, int n) {
    int node = blockIdx.x * 8 + (threadIdx.x >> 5);
    int lane = threadIdx.x & 31;
    if (node >= n) return;
    const float4* hs4 = (const float4*)g_hs;

    int off = g_off[node], cnt = g_cnt[node];
    float4 s = hs4[(size_t)node * 32 + lane];  // self-loop term

    int i = 0;
    for (; i + 4 <= cnt; i += 4) {
        int r0 = g_srt[off + i],     r1 = g_srt[off + i + 1];
        int r2 = g_srt[off + i + 2], r3 = g_srt[off + i + 3];
        float4 a0 = hs4[(size_t)r0 * 32 + lane];
        float4 a1 = hs4[(size_t)r1 * 32 + lane];
        float4 a2 = hs4[(size_t)r2 * 32 + lane];
        float4 a3 = hs4[(size_t)r3 * 32 + lane];
        s.x += (a0.x + a1.x) + (a2.x + a3.x);
        s.y += (a0.y + a1.y) + (a2.y + a3.y);
        s.z += (a0.z + a1.z) + (a2.z + a3.z);
        s.w += (a0.w + a1.w) + (a2.w + a3.w);
    }
    for (; i < cnt; i++) {
        int r = g_srt[off + i];
        float4 a = hs4[(size_t)r * 32 + lane];
        s.x += a.x; s.y += a.y; s.z += a.z; s.w += a.w;
    }

    float dv = rsqrtf((float)(cnt + 1));
    float4 bb = ((const float4*)bias)[lane];
    float4 o;
    o.x = fmaxf(fmaf(s.x, dv, bb.x), 0.f);
    o.y = fmaxf(fmaf(s.y, dv, bb.y), 0.f);
    o.z = fmaxf(fmaf(s.z, dv, bb.z), 0.f);
    o.w = fmaxf(fmaf(s.w, dv, bb.w), 0.f);
    ((float4*)out)[(size_t)node * 32 + lane] = o;
}

// ---------------------------------------------------------------------------
extern "C" void kernel_launch(void* const* d_in, const int* in_sizes, int n_in,
                              void* d_out, int out_size) {
    const float* x  = (const float*)d_in[0];
    const void*  ed = d_in[1];
    const float* W1 = (const float*)d_in[2];
    const float* b1 = (const float*)d_in[3];
    const float* W2 = (const float*)d_in[4];
    const float* b2 = (const float*)d_in[5];
    float* out = (float*)d_out;

    int n = in_sizes[0] / DD;   // 50000
    int E = in_sizes[1] / 2;    // 800000

    const long long* e64 = (const long long*)ed;
    const int*       e32 = (const int*)ed;

    void *h1p, *w1h, *w1l, *w2h, *w2l;
    cudaGetSymbolAddress(&h1p, g_h1);
    cudaGetSymbolAddress(&w1h, g_W1h);
    cudaGetSymbolAddress(&w1l, g_W1l);
    cudaGetSymbolAddress(&w2h, g_W2h);
    cudaGetSymbolAddress(&w2l, g_W2l);

    const int SMEM = 4 * 128 * PADH * 2;   // 139264
    cudaFuncSetAttribute(k_gemm, cudaFuncAttributeMaxDynamicSharedMemorySize, SMEM);

    int tiles = (n + TILE_M - 1) / TILE_M;   // 391
    int nb_a  = (n + 7) / 8;                 // 6250

    k_pre<<<65, 256>>>(e64, W1, W2, E, n);
    k_csr<<<NB_CSR, 256>>>(e64, e32, E, n);

    // Layer 1
    k_gemm<<<tiles, 256, SMEM>>>(x, (const __nv_bfloat16*)w1h, (const __nv_bfloat16*)w1l, n);
    k_agg<<<nb_a, 256>>>(b1, (float*)h1p, n);

    // Layer 2
    k_gemm<<<tiles, 256, SMEM>>>((const float*)h1p, (const __nv_bfloat16*)w2h,
                                 (const __nv_bfloat16*)w2l, n);
    k_agg<<<nb_a, 256>>>(b2, out, n);
}

// round 5
// speedup vs baseline: 1.3999x; 1.0149x over previous
#include <cuda_runtime.h>
#include <cuda_bf16.h>
#include <cuda_fp16.h>
#include <cstdint>

#define DD 128
#define NMAX 50048
#define EMAX 1000000
#define TILE_M 128
#define PADH 136            // smem row stride in halves (272 B)
#define NB_CSR 148

// ---------------- device scratch (no allocation allowed) --------------------
__device__ __half g_hs16[(size_t)NMAX * DD]; // dinv-scaled GEMM output, fp16 (gather src)
__device__ float  g_h1[(size_t)NMAX * DD];   // layer-1 activation (fp32)
__device__ int    g_cnt[NMAX];               // in-degree (excl self)
__device__ int    g_off[NMAX];               // CSR offsets
__device__ int    g_cur[NMAX];               // bucket cursors
__device__ int    g_srt[EMAX];               // sources grouped by destination
__device__ int    g_bsum[NB_CSR];
__device__ int    g_idx64;
__device__ int    g_bar_cnt = 0;
__device__ volatile int g_bar_gen = 0;
// W preformatted as bf16 hi/lo, row-major [k][n]
__device__ __nv_bfloat16 g_W1h[16384], g_W1l[16384], g_W2h[16384], g_W2l[16384];

// ---------------- helpers ---------------------------------------------------
__device__ __forceinline__ uint32_t smem_to_u32(const void* p) {
    uint32_t a;
    asm("{ .reg .u64 t; cvta.to.shared.u64 t, %1; cvt.u32.u64 %0, t; }" : "=r"(a) : "l"(p));
    return a;
}
__device__ __forceinline__ void ldsm4(uint32_t* r, uint32_t addr) {
    asm volatile("ldmatrix.sync.aligned.m8n8.x4.shared.b16 {%0,%1,%2,%3}, [%4];"
                 : "=r"(r[0]), "=r"(r[1]), "=r"(r[2]), "=r"(r[3]) : "r"(addr));
}
__device__ __forceinline__ void ldsm4t(uint32_t* r, uint32_t addr) {
    asm volatile("ldmatrix.sync.aligned.m8n8.x4.trans.shared.b16 {%0,%1,%2,%3}, [%4];"
                 : "=r"(r[0]), "=r"(r[1]), "=r"(r[2]), "=r"(r[3]) : "r"(addr));
}
__device__ __forceinline__ void mma16816(float* c, const uint32_t* a, const uint32_t* b) {
    asm volatile(
        "mma.sync.aligned.m16n8k16.row.col.f32.bf16.bf16.f32 "
        "{%0,%1,%2,%3}, {%4,%5,%6,%7}, {%8,%9}, {%0,%1,%2,%3};"
        : "+f"(c[0]), "+f"(c[1]), "+f"(c[2]), "+f"(c[3])
        : "r"(a[0]), "r"(a[1]), "r"(a[2]), "r"(a[3]), "r"(b[0]), "r"(b[1]));
}
__device__ __forceinline__ void gridbar() {
    __syncthreads();
    if (threadIdx.x == 0) {
        __threadfence();
        int g = g_bar_gen;
        if (atomicAdd(&g_bar_cnt, 1) == NB_CSR - 1) {
            g_bar_cnt = 0;
            __threadfence();
            g_bar_gen = g + 1;
        } else {
            while (g_bar_gen == g) __nanosleep(20);
        }
    }
    __syncthreads();
}

// ---------------------------------------------------------------------------
// Persistent CSR build + preprocess, ONE launch:
// P0: zero counters + W bf16 hi/lo split + edge dtype detect
// P1: histogram  P2-P4: scan  P5: bucket
__global__ void __launch_bounds__(256) k_csr(const long long* __restrict__ e64,
                                             const int* __restrict__ e32,
                                             const float* __restrict__ W1,
                                             const float* __restrict__ W2,
                                             int E, int n) {
    __shared__ int sc[352];
    __shared__ int ssum;
    int tid = threadIdx.x, bid = blockIdx.x;
    int gtid = bid * 256 + tid;
    const int stride = NB_CSR * 256;

    // P0a: zero counters
    for (int i = gtid; i < n; i += stride) g_cnt[i] = 0;
    // P0b: W split (16384 elements)
    for (int idx = gtid; idx < 16384; idx += stride) {
        float w1 = W1[idx], w2 = W2[idx];
        __nv_bfloat16 h1 = __float2bfloat16(w1);
        __nv_bfloat16 h2 = __float2bfloat16(w2);
        g_W1h[idx] = h1;
        g_W1l[idx] = __float2bfloat16(w1 - __bfloat162float(h1));
        g_W2h[idx] = h2;
        g_W2l[idx] = __float2bfloat16(w2 - __bfloat162float(h2));
    }
    // P0c: dtype detect (block 0)
    if (bid == 0) {
        __shared__ int bad;
        if (tid == 0) bad = 0;
        __syncthreads();
        int lim = (E < 1024) ? E : 1024;
        for (int j = tid; j < lim; j += 256) {
            long long v = e64[j];
            if (v < 0 || v >= (long long)n) bad = 1;  // benign race
        }
        __syncthreads();
        if (tid == 0) g_idx64 = bad ? 0 : 1;
    }
    gridbar();
    int idx64 = g_idx64;

    // P1: histogram over destinations
    for (int e = gtid; e < E; e += stride) {
        int c = idx64 ? (int)e64[E + e] : e32[E + e];
        atomicAdd(&g_cnt[c], 1);
    }
    gridbar();

    // P2: chunk into smem + block sum
    int chunk = (n + NB_CSR - 1) / NB_CSR;
    int base = bid * chunk;
    int len = n - base; if (len > chunk) len = chunk; if (len < 0) len = 0;
    int s = 0;
    for (int i = tid; i < len; i += 256) { int v = g_cnt[base + i]; sc[i] = v; s += v; }
    if (tid == 0) ssum = 0;
    __syncthreads();
#pragma unroll
    for (int o = 16; o > 0; o >>= 1) s += __shfl_down_sync(0xffffffffu, s, o);
    if ((tid & 31) == 0) atomicAdd(&ssum, s);
    __syncthreads();
    if (tid == 0) g_bsum[bid] = ssum;
    gridbar();

    // P3: scan block sums
    if (bid == 0 && tid == 0) {
        int a = 0;
        for (int i = 0; i < NB_CSR; i++) { int t = g_bsum[i]; g_bsum[i] = a; a += t; }
    }
    gridbar();

    // P4: serial exclusive scan of chunk, store offsets
    if (tid == 0) {
        int a = g_bsum[bid];
        for (int i = 0; i < len; i++) { int t = sc[i]; sc[i] = a; a += t; }
    }
    __syncthreads();
    for (int i = tid; i < len; i += 256) {
        int o = sc[i];
        g_off[base + i] = o;
        g_cur[base + i] = o;
    }
    gridbar();

    // P5: bucket sources by destination
    for (int e = gtid; e < E; e += stride) {
        int r, c;
        if (idx64) { r = (int)e64[e]; c = (int)e64[E + e]; }
        else       { r = e32[e];      c = e32[E + e]; }
        int pos = atomicAdd(&g_cur[c], 1);
        g_srt[pos] = r;
    }
}

// ---------------------------------------------------------------------------
// HMMA split-bf16 GEMM: hs16[r] = fp16( rsqrt(deg[r]) * (A @ W) ).
__global__ void __launch_bounds__(256, 1) k_gemm(
    const float* __restrict__ Asrc,
    const __nv_bfloat16* __restrict__ Wh, const __nv_bfloat16* __restrict__ Wl, int n)
{
    extern __shared__ char smem[];
    const uint32_t SZ = 128 * PADH * 2;
    const uint32_t OFF_AH = 0, OFF_AL = SZ, OFF_WH = 2 * SZ, OFF_WL = 3 * SZ;
    uint32_t sb = smem_to_u32(smem);
    int tid = threadIdx.x, wid = tid >> 5, lane = tid & 31;
    int row0 = blockIdx.x * TILE_M;

    {
        const uint4* sh = (const uint4*)Wh;
        const uint4* sl = (const uint4*)Wl;
#pragma unroll
        for (int i = 0; i < 8; i++) {
            int f = tid + i * 256;
            int k = f >> 4, n8 = (f & 15) * 8;
            uint32_t doff = (uint32_t)k * 272 + n8 * 2;
            *(uint4*)(smem + OFF_WH + doff) = sh[f];
            *(uint4*)(smem + OFF_WL + doff) = sl[f];
        }
    }

    for (int r = wid; r < 128; r += 8) {
        int gr = row0 + r;
        float4 v = make_float4(0.f, 0.f, 0.f, 0.f);
        if (gr < n) v = ((const float4*)Asrc)[(size_t)gr * 32 + lane];
        __nv_bfloat16 hx = __float2bfloat16(v.x), hy = __float2bfloat16(v.y);
        __nv_bfloat16 hz = __float2bfloat16(v.z), hw = __float2bfloat16(v.w);
        __nv_bfloat16 lx = __float2bfloat16(v.x - __bfloat162float(hx));
        __nv_bfloat16 ly = __float2bfloat16(v.y - __bfloat162float(hy));
        __nv_bfloat16 lz = __float2bfloat16(v.z - __bfloat162float(hz));
        __nv_bfloat16 lw = __float2bfloat16(v.w - __bfloat162float(hw));
        uint32_t o = (uint32_t)r * 272 + lane * 8;
        *(__nv_bfloat162*)(smem + OFF_AH + o)     = __nv_bfloat162(hx, hy);
        *(__nv_bfloat162*)(smem + OFF_AH + o + 4) = __nv_bfloat162(hz, hw);
        *(__nv_bfloat162*)(smem + OFF_AL + o)     = __nv_bfloat162(lx, ly);
        *(__nv_bfloat162*)(smem + OFF_AL + o + 4) = __nv_bfloat162(lz, lw);
    }
    __syncthreads();

    int lrow  = (lane & 7) + ((lane >> 3) & 1) * 8;
    int lcol8 = ((lane >> 4) & 1) * 8;
    int mr = wid * 16;
    uint32_t aRow = (uint32_t)(mr + lrow) * 272 + lcol8 * 2;
    uint32_t bRow = (uint32_t)lrow * 272 + lcol8 * 2;

    float acc[16][4];
#pragma unroll
    for (int t = 0; t < 16; t++)
#pragma unroll
        for (int j = 0; j < 4; j++) acc[t][j] = 0.f;

#pragma unroll
    for (int pass = 0; pass < 3; pass++) {
        uint32_t Ab = sb + ((pass == 2) ? OFF_AL : OFF_AH);
        uint32_t Bb = sb + ((pass == 1) ? OFF_WL : OFF_WH);
#pragma unroll
        for (int kb = 0; kb < 8; kb++) {
            uint32_t ra[4];
            ldsm4(ra, Ab + aRow + kb * 32);
            uint32_t bk = Bb + bRow + (uint32_t)kb * 16 * 272;
#pragma unroll
            for (int nb = 0; nb < 8; nb++) {
                uint32_t rb[4];
                ldsm4t(rb, bk + nb * 32);
                mma16816(acc[2 * nb],     ra, rb);
                mma16816(acc[2 * nb + 1], ra, rb + 2);
            }
        }
    }

    int g = lane >> 2, tig = lane & 3;
    int r0g = row0 + mr + g, r1g = r0g + 8;
    float dv0 = (r0g < n) ? rsqrtf((float)(g_cnt[r0g] + 1)) : 0.f;
    float dv1 = (r1g < n) ? rsqrtf((float)(g_cnt[r1g] + 1)) : 0.f;
#pragma unroll
    for (int t = 0; t < 16; t++) {
        int col = t * 8 + tig * 2;
        if (r0g < n)
            *(__half2*)(g_hs16 + (size_t)r0g * 128 + col) =
                __float22half2_rn(make_float2(acc[t][0] * dv0, acc[t][1] * dv0));
        if (r1g < n)
            *(__half2*)(g_hs16 + (size_t)r1g * 128 + col) =
                __float22half2_rn(make_float2(acc[t][2] * dv1, acc[t][3] * dv1));
    }
}

// ---------------------------------------------------------------------------
// Pull aggregation + epilogue: out[c] = relu(dinv[c]*(hs[c] + sum_nbr hs[r]) + b)
// One warp per node; lane owns 4 halves (8 B) of the 256 B fp16 row.
__global__ void __launch_bounds__(256) k_agg(const float* __restrict__ bias,
                                             float* __restrict__ out, int n) {
    int node = blockIdx.x * 8 + (threadIdx.x >> 5);
    int lane = threadIdx.x & 31;
    if (node >= n) return;
    const uint2* hs2 = (const uint2*)g_hs16;   // 4 halves per uint2

    int off = g_off[node], cnt = g_cnt[node];

    uint2 p = hs2[(size_t)node * 32 + lane];   // self-loop term
    float2 lo = __half22float2(*(const __half2*)&p.x);
    float2 hi = __half22float2(*(const __half2*)&p.y);
    float4 s = make_float4(lo.x, lo.y, hi.x, hi.y);

    int i = 0;
    for (; i + 4 <= cnt; i += 4) {
        int r0 = g_srt[off + i],     r1 = g_srt[off + i + 1];
        int r2 = g_srt[off + i + 2], r3 = g_srt[off + i + 3];
        uint2 q0 = hs2[(size_t)r0 * 32 + lane];
        uint2 q1 = hs2[(size_t)r1 * 32 + lane];
        uint2 q2 = hs2[(size_t)r2 * 32 + lane];
        uint2 q3 = hs2[(size_t)r3 * 32 + lane];
        float2 a0 = __half22float2(*(const __half2*)&q0.x), b0 = __half22float2(*(const __half2*)&q0.y);
        float2 a1 = __half22float2(*(const __half2*)&q1.x), b1 = __half22float2(*(const __half2*)&q1.y);
        float2 a2 = __half22float2(*(const __half2*)&q2.x), b2 = __half22float2(*(const __half2*)&q2.y);
        float2 a3 = __half22float2(*(const __half2*)&q3.x), b3 = __half22float2(*(const __half2*)&q3.y);
        s.x += (a0.x + a1.x) + (a2.x + a3.x);
        s.y += (a0.y + a1.y) + (a2.y + a3.y);
        s.z += (b0.x + b1.x) + (b2.x + b3.x);
        s.w += (b0.y + b1.y) + (b2.y + b3.y);
    }
    for (; i < cnt; i++) {
        int r = g_srt[off + i];
        uint2 q = hs2[(size_t)r * 32 + lane];
        float2 a = __half22float2(*(const __half2*)&q.x);
        float2 b = __half22float2(*(const __half2*)&q.y);
        s.x += a.x; s.y += a.y; s.z += b.x; s.w += b.y;
    }

    float dv = rsqrtf((float)(cnt + 1));
    float2 bb = ((const float2*)bias)[lane * 2];
    float2 bc = ((const float2*)bias)[lane * 2 + 1];
    float4 o;
    o.x = fmaxf(fmaf(s.x, dv, bb.x), 0.f);
    o.y = fmaxf(fmaf(s.y, dv, bb.y), 0.f);
    o.z = fmaxf(fmaf(s.z, dv, bc.x), 0.f);
    o.w = fmaxf(fmaf(s.w, dv, bc.y), 0.f);
    ((float4*)out)[(size_t)node * 32 + lane] = o;
}

// ---------------------------------------------------------------------------
extern "C" void kernel_launch(void* const* d_in, const int* in_sizes, int n_in,
                              void* d_out, int out_size) {
    const float* x  = (const float*)d_in[0];
    const void*  ed = d_in[1];
    const float* W1 = (const float*)d_in[2];
    const float* b1 = (const float*)d_in[3];
    const float* W2 = (const float*)d_in[4];
    const float* b2 = (const float*)d_in[5];
    float* out = (float*)d_out;

    int n = in_sizes[0] / DD;   // 50000
    int E = in_sizes[1] / 2;    // 800000

    const long long* e64 = (const long long*)ed;
    const int*       e32 = (const int*)ed;

    void *h1p, *w1h, *w1l, *w2h, *w2l;
    cudaGetSymbolAddress(&h1p, g_h1);
    cudaGetSymbolAddress(&w1h, g_W1h);
    cudaGetSymbolAddress(&w1l, g_W1l);
    cudaGetSymbolAddress(&w2h, g_W2h);
    cudaGetSymbolAddress(&w2l, g_W2l);

    const int SMEM = 4 * 128 * PADH * 2;   // 139264
    cudaFuncSetAttribute(k_gemm, cudaFuncAttributeMaxDynamicSharedMemorySize, SMEM);

    int tiles = (n + TILE_M - 1) / TILE_M;   // 391
    int nb_a  = (n + 7) / 8;                 // 6250

    k_csr<<<NB_CSR, 256>>>(e64, e32, W1, W2, E, n);

    // Layer 1
    k_gemm<<<tiles, 256, SMEM>>>(x, (const __nv_bfloat16*)w1h, (const __nv_bfloat16*)w1l, n);
    k_agg<<<nb_a, 256>>>(b1, (float*)h1p, n);

    // Layer 2
    k_gemm<<<tiles, 256, SMEM>>>((const float*)h1p, (const __nv_bfloat16*)w2h,
                                 (const __nv_bfloat16*)w2l, n);
    k_agg<<<nb_a, 256>>>(b2, out, n);
}